// round 6
// baseline (speedup 1.0000x reference)
#include <cuda_runtime.h>
#include <cuda_bf16.h>

// Output[b,s,:] == mean(knowledge, axis=0) for every (b,s):
// top_k with max_chunks == K selects a permutation of ALL knowledge rows,
// so mean(take(knowledge, top_k), axis=1) == mean(knowledge, axis=0).
//
// R1-R5 evidence: total dur_us pinned at 8.927999us across five kernel
// variants (profiled 5.6-10.75us) -> harness replay floor. This round
// minimizes true kernel cost: 64 CTAs (vs 256) cuts redundant knowledge
// reads 4x (32MB -> 8MB cold-cache traffic), each CTA computes the mean
// via a 4-way warp-group split (16 loads/thread, one latency exposure)
// and writes 64 identical output rows.

#define E_DIM 512
#define K_ROWS 64
#define THREADS 512            // 4 groups of 128; 128 float4 columns
#define ROWS_PER_CTA 64        // 4096 / 64 = 64 CTAs
#define COLS4 (E_DIM / 4)      // 128 float4 per row

__global__ void __launch_bounds__(THREADS)
fused_mean_broadcast(const float4* __restrict__ knowledge4,
                     float4* __restrict__ out, int rows) {
    __shared__ float4 part[4 * COLS4];   // 4 partial sums per column, 8KB

    int t = threadIdx.x;
    int c = t & (COLS4 - 1);   // column 0..127
    int q = t >> 7;            // group 0..3

    // Group q sums knowledge rows [16q, 16q+16) of its column:
    // 16 independent fully-unrolled loads -> one exposed memory latency.
    float4 s = make_float4(0.f, 0.f, 0.f, 0.f);
#pragma unroll
    for (int k = 0; k < K_ROWS / 4; ++k) {
        float4 a = knowledge4[(q * (K_ROWS / 4) + k) * COLS4 + c];
        s.x += a.x; s.y += a.y; s.z += a.z; s.w += a.w;
    }
    part[q * COLS4 + c] = s;
    __syncthreads();

    // Full column mean from the 4 partials (3 float4 adds from smem).
    float4 p0 = part[0 * COLS4 + c];
    float4 p1 = part[1 * COLS4 + c];
    float4 p2 = part[2 * COLS4 + c];
    float4 p3 = part[3 * COLS4 + c];
    const float inv = 1.0f / (float)K_ROWS;
    float4 m;
    m.x = (p0.x + p1.x + p2.x + p3.x) * inv;
    m.y = (p0.y + p1.y + p2.y + p3.y) * inv;
    m.z = (p0.z + p1.z + p2.z + p3.z) * inv;
    m.w = (p0.w + p1.w + p2.w + p3.w) * inv;

    // CTA writes 64 identical rows; group q writes rows [16q, 16q+16).
    int r0 = blockIdx.x * ROWS_PER_CTA + q * (ROWS_PER_CTA / 4);
    size_t base = (size_t)r0 * COLS4 + c;
#pragma unroll
    for (int r = 0; r < ROWS_PER_CTA / 4; ++r) {
        if (r0 + r < rows)
            out[base + (size_t)r * COLS4] = m;
    }
}

extern "C" void kernel_launch(void* const* d_in, const int* in_sizes, int n_in,
                              void* d_out, int out_size) {
    // d_in[0]: query_embedding [4,1024,512] f32 (unused — output is query-independent)
    // d_in[1]: knowledge [64,512] f32
    const float* knowledge = (const float*)d_in[1];
    float* out = (float*)d_out;

    int rows = out_size / E_DIM;                           // 4096
    int blocks = (rows + ROWS_PER_CTA - 1) / ROWS_PER_CTA; // 64

    fused_mean_broadcast<<<blocks, THREADS>>>(
        reinterpret_cast<const float4*>(knowledge),
        reinterpret_cast<float4*>(out), rows);
}

// round 7
// speedup vs baseline: 1.3527x; 1.3527x over previous
#include <cuda_runtime.h>
#include <cuda_bf16.h>

// Output[b,s,:] == mean(knowledge, axis=0) for every (b,s):
// top_k with max_chunks == K selects a permutation of ALL knowledge rows,
// so mean(take(knowledge, top_k), axis=1) == mean(knowledge, axis=0).
//
// R1-R6 evidence: total dur_us pinned at 8.93 +/- 0.03us across six
// structurally different kernels (profiled 5.6-10.8us) -> harness
// graph-replay floor; the 8.7us reading is noise. This round minimizes
// warm-cache time + ramp jointly: 128 CTAs x 512 threads (~one full
// wave), 4-way warp-group K-split (16 loads/thread critical path),
// 8 STG.128/thread store tail, 32 rows per CTA.

#define E_DIM 512
#define K_ROWS 64
#define THREADS 512            // 4 groups of 128; 128 float4 columns
#define ROWS_PER_CTA 32        // 4096 / 32 = 128 CTAs (~one wave)
#define COLS4 (E_DIM / 4)      // 128 float4 per row

__global__ void __launch_bounds__(THREADS)
fused_mean_broadcast(const float4* __restrict__ knowledge4,
                     float4* __restrict__ out, int rows) {
    __shared__ float4 part[4 * COLS4];   // 4 partial sums per column, 8KB

    int t = threadIdx.x;
    int c = t & (COLS4 - 1);   // column 0..127
    int q = t >> 7;            // group 0..3

    // Group q sums knowledge rows [16q, 16q+16) of its column:
    // 16 independent fully-unrolled loads -> one exposed memory latency.
    float4 s = make_float4(0.f, 0.f, 0.f, 0.f);
#pragma unroll
    for (int k = 0; k < K_ROWS / 4; ++k) {
        float4 a = knowledge4[(q * (K_ROWS / 4) + k) * COLS4 + c];
        s.x += a.x; s.y += a.y; s.z += a.z; s.w += a.w;
    }
    part[q * COLS4 + c] = s;
    __syncthreads();

    // Full column mean from the 4 partials (3 float4 adds from smem).
    float4 p0 = part[0 * COLS4 + c];
    float4 p1 = part[1 * COLS4 + c];
    float4 p2 = part[2 * COLS4 + c];
    float4 p3 = part[3 * COLS4 + c];
    const float inv = 1.0f / (float)K_ROWS;
    float4 m;
    m.x = (p0.x + p1.x + p2.x + p3.x) * inv;
    m.y = (p0.y + p1.y + p2.y + p3.y) * inv;
    m.z = (p0.z + p1.z + p2.z + p3.z) * inv;
    m.w = (p0.w + p1.w + p2.w + p3.w) * inv;

    // CTA writes 32 identical rows; group q writes rows [8q, 8q+8).
    int r0 = blockIdx.x * ROWS_PER_CTA + q * (ROWS_PER_CTA / 4);
    size_t base = (size_t)r0 * COLS4 + c;
#pragma unroll
    for (int r = 0; r < ROWS_PER_CTA / 4; ++r) {
        if (r0 + r < rows)
            out[base + (size_t)r * COLS4] = m;
    }
}

extern "C" void kernel_launch(void* const* d_in, const int* in_sizes, int n_in,
                              void* d_out, int out_size) {
    // d_in[0]: query_embedding [4,1024,512] f32 (unused — output is query-independent)
    // d_in[1]: knowledge [64,512] f32
    const float* knowledge = (const float*)d_in[1];
    float* out = (float*)d_out;

    int rows = out_size / E_DIM;                           // 4096
    int blocks = (rows + ROWS_PER_CTA - 1) / ROWS_PER_CTA; // 128

    fused_mean_broadcast<<<blocks, THREADS>>>(
        reinterpret_cast<const float4*>(knowledge),
        reinterpret_cast<float4*>(out), rows);
}